// round 1
// baseline (speedup 1.0000x reference)
#include <cuda_runtime.h>
#include <math.h>
#include <stdint.h>
#include <stddef.h>

#define BATCH 2048
#define SEQ   64
#define CH    384
#define NH    12
#define HD    32
#define TPB   256
#define XS_S  388   // x smem row stride (floats), 16B-aligned, bank-skewed
#define WS_S  194   // weight/qkv smem row stride (floats), 8B-aligned, bank-skewed

// 201 MB scratch for the per-head attention output t = q @ M  (B, N, C)
__device__ float g_t[(size_t)BATCH * SEQ * CH];

static __device__ __forceinline__ unsigned long long pack2(float lo, float hi) {
    unsigned long long r;
    asm("mov.b64 %0, {%1, %2};" : "=l"(r) : "f"(lo), "f"(hi));
    return r;
}
static __device__ __forceinline__ void fma2(unsigned long long &acc,
                                            unsigned long long a,
                                            unsigned long long b) {
    // packed dual fp32 FMA (Blackwell): acc.xy += a.xy * b.xy
    asm("fma.rn.f32x2 %0, %1, %2, %0;" : "+l"(acc) : "l"(a), "l"(b));
}
static __device__ __forceinline__ float2 unpack2(unsigned long long v) {
    float lo, hi;
    asm("mov.b64 {%0, %1}, %2;" : "=f"(lo), "=f"(hi) : "l"(v));
    return make_float2(lo, hi);
}
static __device__ __forceinline__ unsigned long long f2ull(float2 v) {
    return pack2(v.x, v.y);
}

// ---------------------------------------------------------------------------
// Kernel 1: per-batch fused qkv GEMM + dual-lambda linear attention -> g_t
// One CTA per batch element. 6 passes x 2 heads.
// ---------------------------------------------------------------------------
__global__ __launch_bounds__(TPB, 1)
void attn_k1(const float* __restrict__ x, const float* __restrict__ qkv_w,
             const float* __restrict__ qkv_b,
             const float* __restrict__ lk1, const float* __restrict__ lv1,
             const float* __restrict__ lk2, const float* __restrict__ lv2)
{
    extern __shared__ float sm[];
    float* xs   = sm;                 // [64][XS_S]   x_b tile
    float* ws   = sm + SEQ * XS_S;    // [64][WS_S]   weight chunk / qkv / M / t
    float* lamc = ws + SEQ * WS_S;    // [12]         (1-lambda_h)*scale

    const int t  = threadIdx.x;
    const int b  = blockIdx.x;
    const int ty = t >> 5;            // 0..7  -> output rows ty*8..ty*8+7
    const int tx = t & 31;            // 0..31 -> output cols tx*6..tx*6+5

    // per-head gate coefficients (redundant per CTA, trivial cost)
    if (t < NH) {
        float s1 = 0.f, s2 = 0.f;
        #pragma unroll
        for (int i = 0; i < HD; i++) {
            s1 += lk1[t*HD+i] * lv1[t*HD+i];
            s2 += lk2[t*HD+i] * lv2[t*HD+i];
        }
        float lam = expf(s1) - expf(s2) + 0.35550906759096926f; // lambda_init
        lamc[t] = (1.0f - lam) * 0.1767766952966369f;           // * d^-0.5
    }

    // stage x_b (64x384) into smem
    {
        const float4* xg = reinterpret_cast<const float4*>(x + (size_t)b * SEQ * CH);
        #pragma unroll
        for (int i = 0; i < 24; i++) {
            int idx = t + i * TPB;          // 0..6143 float4s
            int r = idx / 96, c4 = idx % 96;
            float4 v = xg[idx];
            *reinterpret_cast<float4*>(&xs[r * XS_S + c4 * 4]) = v;
        }
    }

    #pragma unroll 1
    for (int pass = 0; pass < 6; pass++) {
        const int h0 = pass * 2;

        // ---- qkv GEMM: (64x384) @ (384x192) for heads h0, h0+1 ----
        unsigned long long acc[8][3];
        #pragma unroll
        for (int i = 0; i < 8; i++)
            #pragma unroll
            for (int j = 0; j < 3; j++) acc[i][j] = 0ull;

        #pragma unroll 1
        for (int kt = 0; kt < CH; kt += 64) {
            __syncthreads();   // ws region free (prev pass / prev chunk done)
            // load weight chunk: ws[kk][seg*64 + hp*32 + c]
            #pragma unroll
            for (int seg = 0; seg < 3; seg++) {
                #pragma unroll
                for (int hp = 0; hp < 2; hp++) {
                    const float* src = qkv_w + (size_t)(kt + ty*8) * 1152
                                       + seg*384 + (h0+hp)*HD + tx;
                    float* dst = ws + (ty*8) * WS_S + seg*64 + hp*HD + tx;
                    #pragma unroll
                    for (int i = 0; i < 8; i++)
                        dst[i * WS_S] = src[(size_t)i * 1152];
                }
            }
            __syncthreads();
            #pragma unroll
            for (int kk = 0; kk < 64; kk += 4) {
                unsigned long long wp[4][3];
                #pragma unroll
                for (int q4 = 0; q4 < 4; q4++) {
                    const float2* wrow =
                        reinterpret_cast<const float2*>(&ws[(kk+q4)*WS_S + tx*6]);
                    #pragma unroll
                    for (int j = 0; j < 3; j++) wp[q4][j] = f2ull(wrow[j]);
                }
                #pragma unroll
                for (int i = 0; i < 8; i++) {
                    float4 xv = *reinterpret_cast<const float4*>(
                        &xs[(ty*8+i)*XS_S + kt + kk]);
                    unsigned long long a0 = pack2(xv.x, xv.x);
                    unsigned long long a1 = pack2(xv.y, xv.y);
                    unsigned long long a2 = pack2(xv.z, xv.z);
                    unsigned long long a3 = pack2(xv.w, xv.w);
                    #pragma unroll
                    for (int j = 0; j < 3; j++) {
                        fma2(acc[i][j], a0, wp[0][j]);
                        fma2(acc[i][j], a1, wp[1][j]);
                        fma2(acc[i][j], a2, wp[2][j]);
                        fma2(acc[i][j], a3, wp[3][j]);
                    }
                }
            }
        }
        __syncthreads();

        // write qkv (+bias) into ws: cols [q0 q1 | k0 k1 | v0 v1] x 32
        #pragma unroll
        for (int j = 0; j < 3; j++) {
            int cc  = tx*6 + 2*j;       // even -> pair never crosses a 32-col seg
            int seg = cc >> 6;
            int rem = cc & 63;
            int hp  = rem >> 5;
            int c   = rem & 31;
            int gcol = seg*384 + (h0+hp)*HD + c;
            float b0 = qkv_b[gcol], b1 = qkv_b[gcol+1];
            #pragma unroll
            for (int i = 0; i < 8; i++) {
                float2 v = unpack2(acc[i][j]);
                ws[(ty*8+i)*WS_S + cc]     = v.x + b0;
                ws[(ty*8+i)*WS_S + cc + 1] = v.y + b1;
            }
        }
        __syncthreads();

        // feature map f(x)= x>=0 ? x+1 : exp(x) in-place on k,v cols (64..191)
        #pragma unroll
        for (int i = 0; i < 32; i++) {
            int idx = t + i*TPB;          // 0..8191
            int r = idx >> 7;
            int c = 64 + (idx & 127);
            float v = ws[r*WS_S + c];
            ws[r*WS_S + c] = (v >= 0.f) ? (v + 1.f) : expf(v);
        }
        __syncthreads();

        #pragma unroll 1
        for (int hp = 0; hp < 2; hp++) {
            const int h = h0 + hp;

            // A[d][e] = sum_n f(k[n][d]) * f(v[n][e])
            const int dA = t >> 3;          // 0..31
            const int e4 = (t & 7) * 4;     // 0,4,...,28
            float a0=0.f, a1=0.f, a2=0.f, a3=0.f;
            {
                const float* kc = ws + 64  + hp*HD + dA;
                const float* vc = ws + 128 + hp*HD + e4;
                #pragma unroll 8
                for (int n = 0; n < SEQ; n++) {
                    float fk = kc[n*WS_S];
                    a0 += fk * vc[n*WS_S+0];
                    a1 += fk * vc[n*WS_S+1];
                    a2 += fk * vc[n*WS_S+2];
                    a3 += fk * vc[n*WS_S+3];
                }
            }
            float coef = lamc[h];
            __syncthreads();   // A reads done; k-region of this head reusable

            // M[d][e] = A * gauss(d,e) * (1-lambda)*scale  -> k-region rows 0..31
            {
                float av[4] = {a0, a1, a2, a3};
                #pragma unroll
                for (int j = 0; j < 4; j++) {
                    float diff = (float)(dA - (e4 + j));
                    float g = expf(-2.0f * diff * diff);   // sigma = 0.5
                    ws[dA*WS_S + 64 + hp*HD + e4 + j] = av[j] * g * coef;
                }
            }
            __syncthreads();

            // t[r][c] = sum_d q[r][d] * M[d][c]  -> global scratch
            {
                const int r  = t >> 2;          // 0..63
                const int c8 = (t & 3) * 8;     // 0,8,16,24
                float tv[8];
                #pragma unroll
                for (int j = 0; j < 8; j++) tv[j] = 0.f;
                const float* qrow = ws + r*WS_S + hp*HD;
                const float* Mb   = ws + 64 + hp*HD + c8;
                #pragma unroll 8
                for (int dd = 0; dd < HD; dd++) {
                    float qv = qrow[dd];
                    #pragma unroll
                    for (int j = 0; j < 8; j++)
                        tv[j] += qv * Mb[dd*WS_S + j];
                }
                float* dst = g_t + ((size_t)b*SEQ + r)*CH + h*HD + c8;
                #pragma unroll
                for (int j = 0; j < 8; j++) dst[j] = tv[j];
            }
        }
        // next pass begins with __syncthreads() before ws reload
    }
}

// ---------------------------------------------------------------------------
// Kernel 2: out = g_t (131072x384) @ proj_w (384x384) + proj_b
// Grid: (2048 row-blocks of 64) x (2 col-blocks of 192)
// ---------------------------------------------------------------------------
__global__ __launch_bounds__(TPB, 1)
void attn_k2(const float* __restrict__ pw, const float* __restrict__ pb,
             float* __restrict__ out)
{
    extern __shared__ float sm[];
    float* As = sm;            // [64][68]
    float* Bs = sm + 64*68;    // [64][WS_S]
    const int t  = threadIdx.x;
    const int rb = blockIdx.x;
    const int cb = blockIdx.y;
    const int ty = t >> 5;
    const int tx = t & 31;

    unsigned long long acc[8][3];
    #pragma unroll
    for (int i = 0; i < 8; i++)
        #pragma unroll
        for (int j = 0; j < 3; j++) acc[i][j] = 0ull;

    const float* Ag = g_t + (size_t)rb * SEQ * CH;

    #pragma unroll 1
    for (int kt = 0; kt < CH; kt += 64) {
        __syncthreads();
        #pragma unroll
        for (int i = 0; i < 4; i++) {
            int idx = t + i*TPB;            // 0..1023 float4s
            int r = idx >> 4, c4 = idx & 15;
            float4 v = *reinterpret_cast<const float4*>(
                Ag + (size_t)r*CH + kt + c4*4);
            *reinterpret_cast<float4*>(&As[r*68 + c4*4]) = v;
        }
        #pragma unroll
        for (int chk = 0; chk < 6; chk++) {
            const float* src = pw + (size_t)(kt + ty*8)*CH + cb*192 + chk*32 + tx;
            float* dst = Bs + (ty*8)*WS_S + chk*32 + tx;
            #pragma unroll
            for (int i = 0; i < 8; i++)
                dst[i*WS_S] = src[(size_t)i*CH];
        }
        __syncthreads();
        #pragma unroll
        for (int kk = 0; kk < 64; kk += 4) {
            unsigned long long wp[4][3];
            #pragma unroll
            for (int q4 = 0; q4 < 4; q4++) {
                const float2* wrow =
                    reinterpret_cast<const float2*>(&Bs[(kk+q4)*WS_S + tx*6]);
                #pragma unroll
                for (int j = 0; j < 3; j++) wp[q4][j] = f2ull(wrow[j]);
            }
            #pragma unroll
            for (int i = 0; i < 8; i++) {
                float4 xv = *reinterpret_cast<const float4*>(
                    &As[(ty*8+i)*68 + kk]);
                unsigned long long a0 = pack2(xv.x, xv.x);
                unsigned long long a1 = pack2(xv.y, xv.y);
                unsigned long long a2 = pack2(xv.z, xv.z);
                unsigned long long a3 = pack2(xv.w, xv.w);
                #pragma unroll
                for (int j = 0; j < 3; j++) {
                    fma2(acc[i][j], a0, wp[0][j]);
                    fma2(acc[i][j], a1, wp[1][j]);
                    fma2(acc[i][j], a2, wp[2][j]);
                    fma2(acc[i][j], a3, wp[3][j]);
                }
            }
        }
    }

    #pragma unroll
    for (int j = 0; j < 3; j++) {
        int gcol = cb*192 + tx*6 + 2*j;
        float b0 = pb[gcol], b1 = pb[gcol+1];
        #pragma unroll
        for (int i = 0; i < 8; i++) {
            float2 v = unpack2(acc[i][j]);
            float2 o = make_float2(v.x + b0, v.y + b1);
            *reinterpret_cast<float2*>(
                out + (size_t)(rb*SEQ + ty*8 + i)*CH + gcol) = o;
        }
    }
}

extern "C" void kernel_launch(void* const* d_in, const int* in_sizes, int n_in,
                              void* d_out, int out_size) {
    (void)in_sizes; (void)n_in; (void)out_size;
    const float* x      = (const float*)d_in[0];
    const float* qkv_w  = (const float*)d_in[1];
    const float* qkv_b  = (const float*)d_in[2];
    const float* proj_w = (const float*)d_in[3];
    const float* proj_b = (const float*)d_in[4];
    const float* lk1    = (const float*)d_in[5];
    const float* lv1    = (const float*)d_in[6];
    const float* lk2    = (const float*)d_in[7];
    const float* lv2    = (const float*)d_in[8];

    const int smem1 = (SEQ*XS_S + SEQ*WS_S + 16) * (int)sizeof(float); // 149 KB
    const int smem2 = (64*68 + 64*WS_S) * (int)sizeof(float);          // 65.5 KB
    cudaFuncSetAttribute(attn_k1, cudaFuncAttributeMaxDynamicSharedMemorySize, smem1);
    cudaFuncSetAttribute(attn_k2, cudaFuncAttributeMaxDynamicSharedMemorySize, smem2);

    attn_k1<<<BATCH, TPB, smem1>>>(x, qkv_w, qkv_b, lk1, lv1, lk2, lv2);
    attn_k2<<<dim3(BATCH, 2), TPB, smem2>>>(proj_w, proj_b, (float*)d_out);
}

// round 3
// speedup vs baseline: 3.0655x; 3.0655x over previous
#include <cuda_runtime.h>
#include <cuda_fp16.h>
#include <math.h>
#include <stdint.h>
#include <stddef.h>

#define BATCH 2048
#define SEQ   64
#define CH    384
#define NH    12
#define HD    32
#define MTOT  (BATCH*SEQ)      // 131072
#define NQKV  (3*CH)           // 1152

// ---------------- static device scratch ------------------------------------
__device__ __half g_xh  [(size_t)MTOT * CH];     // fp16(x)
__device__ __half g_wqh [(size_t)NQKV * CH];     // qkv_w^T hi   [n][k]
__device__ __half g_wql [(size_t)NQKV * CH];     // qkv_w^T lo
__device__ __half g_wph [(size_t)CH * CH];       // proj_w^T hi
__device__ __half g_wpl [(size_t)CH * CH];       // proj_w^T lo
__device__ float  g_qkv [(size_t)MTOT * NQKV];   // fp32 qkv (k,v feature-mapped)
__device__ __half g_t   [(size_t)MTOT * CH];     // fp16 attention output
__device__ float  g_lamc[NH];

// ---------------- PTX helpers ----------------------------------------------
static __device__ __forceinline__ uint32_t smem_u32(const void* p) {
    uint32_t a;
    asm("{ .reg .u64 t; cvta.to.shared.u64 t, %1; cvt.u32.u64 %0, t; }"
        : "=r"(a) : "l"(p));
    return a;
}
static __device__ __forceinline__ void cp_async16(uint32_t dst, const void* src) {
    asm volatile("cp.async.ca.shared.global [%0], [%1], 16;"
                 :: "r"(dst), "l"(src) : "memory");
}
static __device__ __forceinline__ void cp_commit() {
    asm volatile("cp.async.commit_group;" ::: "memory");
}
template <int N>
static __device__ __forceinline__ void cp_wait() {
    asm volatile("cp.async.wait_group %0;" :: "n"(N) : "memory");
}
static __device__ __forceinline__ void ldsm_x4(uint32_t* r, uint32_t addr) {
    asm volatile("ldmatrix.sync.aligned.m8n8.x4.shared.b16 {%0,%1,%2,%3}, [%4];"
                 : "=r"(r[0]), "=r"(r[1]), "=r"(r[2]), "=r"(r[3]) : "r"(addr));
}
static __device__ __forceinline__ void mma16816(float* d, const uint32_t* a,
                                                uint32_t b0, uint32_t b1) {
    asm volatile("mma.sync.aligned.m16n8k16.row.col.f32.f16.f16.f32 "
                 "{%0,%1,%2,%3}, {%4,%5,%6,%7}, {%8,%9}, {%0,%1,%2,%3};"
                 : "+f"(d[0]), "+f"(d[1]), "+f"(d[2]), "+f"(d[3])
                 : "r"(a[0]), "r"(a[1]), "r"(a[2]), "r"(a[3]), "r"(b0), "r"(b1));
}

// ---------------------------------------------------------------------------
// Kernel P: x -> fp16; qkv_w/proj_w -> transposed [n][k] fp16 hi/lo; gate coefs
// ---------------------------------------------------------------------------
__global__ void prep_kernel(const float* __restrict__ x,
                            const float* __restrict__ qkv_w,
                            const float* __restrict__ proj_w,
                            const float* __restrict__ lk1, const float* __restrict__ lv1,
                            const float* __restrict__ lk2, const float* __restrict__ lv2)
{
    const long long XN4 = (long long)MTOT * CH / 4;
    const long long WQ  = (long long)NQKV * CH;
    const long long WP  = (long long)CH * CH;
    const long long TOT = XN4 + WQ + WP + NH;
    long long stride = (long long)gridDim.x * blockDim.x;
    for (long long i = (long long)blockIdx.x * blockDim.x + threadIdx.x;
         i < TOT; i += stride) {
        if (i < XN4) {
            float4 v = __ldg(((const float4*)x) + i);
            __half2 p0 = __floats2half2_rn(v.x, v.y);
            __half2 p1 = __floats2half2_rn(v.z, v.w);
            uint2 pk;
            pk.x = *(uint32_t*)&p0;
            pk.y = *(uint32_t*)&p1;
            ((uint2*)g_xh)[i] = pk;
        } else if (i < XN4 + WQ) {
            long long j = i - XN4;
            int n = (int)(j / CH), k = (int)(j % CH);
            float w = __ldg(qkv_w + (size_t)k * NQKV + n);
            __half h = __float2half_rn(w);
            g_wqh[j] = h;
            g_wql[j] = __float2half_rn(w - __half2float(h));
        } else if (i < XN4 + WQ + WP) {
            long long j = i - XN4 - WQ;
            int n = (int)(j / CH), k = (int)(j % CH);
            float w = __ldg(proj_w + (size_t)k * CH + n);
            __half h = __float2half_rn(w);
            g_wph[j] = h;
            g_wpl[j] = __float2half_rn(w - __half2float(h));
        } else {
            int h = (int)(i - XN4 - WQ - WP);
            float s1 = 0.f, s2 = 0.f;
            for (int q = 0; q < HD; q++) {
                s1 += lk1[h*HD+q] * lv1[h*HD+q];
                s2 += lk2[h*HD+q] * lv2[h*HD+q];
            }
            float lam = expf(s1) - expf(s2) + 0.35550906759096926f;
            g_lamc[h] = (1.0f - lam) * 0.1767766952966369f;
        }
    }
}

// ---------------------------------------------------------------------------
// mma.sync GEMM: C[M, N] = A[M, K=384] @ B^T + bias,  B stored [N][K] hi/lo
// CTA 128x128, 8 warps (2x4), warp tile 64x32, K chunks of 32, double buffer.
// mode 0: qkv epilogue (feature map for blockIdx.x >= 3); mode 1: plain.
// ---------------------------------------------------------------------------
#define RS        40                 // smem row stride in halves (80 B)
#define TILE_H    (128 * RS)         // halves per 128-row tile
#define STAGE_H   (3 * TILE_H)       // A, Bh, Bl
#define STAGE_B   (STAGE_H * 2)      // bytes per stage (30720)
#define GEMM_SMEM (2 * STAGE_B)

__global__ __launch_bounds__(256)
void gemm_f16(const __half* __restrict__ A,
              const __half* __restrict__ Bh,
              const __half* __restrict__ Bl,
              const float* __restrict__ bias,
              float* __restrict__ C, int ldc, int mode)
{
    extern __shared__ __half sm[];
    const uint32_t sbase = smem_u32(sm);
    const int tid  = threadIdx.x;
    const int lane = tid & 31;
    const int wid  = tid >> 5;
    const int wm   = wid >> 2;        // 0..1
    const int wn   = wid & 3;         // 0..3
    const int arow = blockIdx.y * 128;
    const int brow = blockIdx.x * 128;

    // cp.async indexing (6 x 16B per thread per stage)
    int ld_arr[6], ld_row[6], ld_seg[6];
    #pragma unroll
    for (int i = 0; i < 6; i++) {
        int e = tid + i * 256;        // 0..1535
        ld_arr[i] = e >> 9;           // 0:A 1:Bh 2:Bl
        int idx = e & 511;
        ld_row[i] = idx >> 2;
        ld_seg[i] = idx & 3;
    }

    auto load_stage = [&](int c, int s) {
        const uint32_t stg = sbase + s * STAGE_B;
        #pragma unroll
        for (int i = 0; i < 6; i++) {
            const __half* gsrc;
            int row = ld_row[i];
            if (ld_arr[i] == 0)      gsrc = A  + (size_t)(arow + row) * CH;
            else if (ld_arr[i] == 1) gsrc = Bh + (size_t)(brow + row) * CH;
            else                     gsrc = Bl + (size_t)(brow + row) * CH;
            gsrc += c * 32 + ld_seg[i] * 8;
            uint32_t dst = stg + (ld_arr[i] * TILE_H + row * RS + ld_seg[i] * 8) * 2;
            cp_async16(dst, gsrc);
        }
        cp_commit();
    };

    float acc[4][4][4];
    #pragma unroll
    for (int a = 0; a < 4; a++)
        #pragma unroll
        for (int b = 0; b < 4; b++)
            #pragma unroll
            for (int cdx = 0; cdx < 4; cdx++) acc[a][b][cdx] = 0.f;

    // per-lane ldmatrix base addresses (bytes)
    // A: row = wm*64 + (lane&15), kseg = lane>>4
    const uint32_t aBase = ((wm * 64 + (lane & 15)) * RS + (lane >> 4) * 8) * 2;
    // B: row = wn*32 + (lane&7) + (lane>>4)*8, kseg = (lane>>3)&1
    const uint32_t bRowOff = ((wn * 32 + (lane & 7) + (lane >> 4) * 8) * RS
                              + ((lane >> 3) & 1) * 8) * 2;

    load_stage(0, 0);

    #pragma unroll 1
    for (int c = 0; c < 12; c++) {
        const int s = c & 1;
        if (c < 11) load_stage(c + 1, s ^ 1);
        if (c < 11) cp_wait<1>(); else cp_wait<0>();
        __syncthreads();

        const uint32_t stg = sbase + s * STAGE_B;
        #pragma unroll
        for (int ks = 0; ks < 2; ks++) {
            uint32_t afr[4][4], bhf[2][4], blf[2][4];
            #pragma unroll
            for (int mt = 0; mt < 4; mt++)
                ldsm_x4(afr[mt], stg + aBase + mt * (16 * RS * 2) + ks * 32);
            #pragma unroll
            for (int nt2 = 0; nt2 < 2; nt2++) {
                ldsm_x4(bhf[nt2], stg + TILE_H * 2 + bRowOff
                                  + nt2 * (16 * RS * 2) + ks * 32);
                ldsm_x4(blf[nt2], stg + TILE_H * 4 + bRowOff
                                  + nt2 * (16 * RS * 2) + ks * 32);
            }
            #pragma unroll
            for (int mt = 0; mt < 4; mt++)
                #pragma unroll
                for (int nt = 0; nt < 4; nt++) {
                    mma16816(acc[mt][nt], afr[mt],
                             bhf[nt >> 1][(nt & 1) * 2], bhf[nt >> 1][(nt & 1) * 2 + 1]);
                    mma16816(acc[mt][nt], afr[mt],
                             blf[nt >> 1][(nt & 1) * 2], blf[nt >> 1][(nt & 1) * 2 + 1]);
                }
        }
        __syncthreads();
    }

    // epilogue
    const bool fmap = (mode == 0) && (blockIdx.x >= 3);
    #pragma unroll
    for (int mt = 0; mt < 4; mt++) {
        const int r0 = arow + wm * 64 + mt * 16 + (lane >> 2);
        #pragma unroll
        for (int nt = 0; nt < 4; nt++) {
            const int n = brow + wn * 32 + nt * 8 + (lane & 3) * 2;
            const float b0 = __ldg(bias + n), b1 = __ldg(bias + n + 1);
            #pragma unroll
            for (int half_ = 0; half_ < 2; half_++) {
                float v0 = acc[mt][nt][half_ * 2 + 0] + b0;
                float v1 = acc[mt][nt][half_ * 2 + 1] + b1;
                if (fmap) {
                    v0 = (v0 >= 0.f) ? v0 + 1.f : expf(v0);
                    v1 = (v1 >= 0.f) ? v1 + 1.f : expf(v1);
                }
                *reinterpret_cast<float2*>(
                    C + (size_t)(r0 + half_ * 8) * ldc + n) = make_float2(v0, v1);
            }
        }
    }
}

// ---------------------------------------------------------------------------
// Kernel B: per (b,h): A = f(k)^T f(v); M = A*gauss*coef; t = q @ M -> fp16
// grid (2048, 12), 128 threads
// ---------------------------------------------------------------------------
__global__ __launch_bounds__(128, 8)
void mid_kernel()
{
    __shared__ float qs[64 * 33], ks[64 * 33], vs[64 * 33];
    __shared__ float Ms[32 * 33];
    __shared__ float gtab[32];

    const int tid = threadIdx.x;
    const int b = blockIdx.x, h = blockIdx.y;

    if (tid < 32) gtab[tid] = expf(-2.0f * (float)(tid * tid));
    const float coef = g_lamc[h];

    const float* gbase = g_qkv + (size_t)b * 64 * NQKV + h * HD;
    #pragma unroll
    for (int arr = 0; arr < 3; arr++) {
        float* dst = (arr == 0) ? qs : (arr == 1) ? ks : vs;
        const float* src = gbase + arr * CH;
        #pragma unroll
        for (int i = 0; i < 4; i++) {
            int idx = tid + i * 128;
            int r = idx >> 3, g = idx & 7;
            float4 v = __ldg((const float4*)(src + (size_t)r * NQKV) + g);
            dst[r * 33 + g * 4 + 0] = v.x;
            dst[r * 33 + g * 4 + 1] = v.y;
            dst[r * 33 + g * 4 + 2] = v.z;
            dst[r * 33 + g * 4 + 3] = v.w;
        }
    }
    __syncthreads();

    {
        const int d = tid >> 2;
        const int e8 = (tid & 3) * 8;
        float acc[8];
        #pragma unroll
        for (int j = 0; j < 8; j++) acc[j] = 0.f;
        #pragma unroll 8
        for (int n = 0; n < 64; n++) {
            float fk = ks[n * 33 + d];
            #pragma unroll
            for (int j = 0; j < 8; j++)
                acc[j] += fk * vs[n * 33 + e8 + j];
        }
        #pragma unroll
        for (int j = 0; j < 8; j++) {
            int e = e8 + j;
            int ad = (d > e) ? (d - e) : (e - d);
            Ms[d * 33 + e] = acc[j] * gtab[ad] * coef;
        }
    }
    __syncthreads();

    {
        const int r = tid >> 1;
        const int c16 = (tid & 1) * 16;
        float acc[16];
        #pragma unroll
        for (int j = 0; j < 16; j++) acc[j] = 0.f;
        #pragma unroll 8
        for (int d = 0; d < 32; d++) {
            float qv = qs[r * 33 + d];
            #pragma unroll
            for (int j = 0; j < 16; j++)
                acc[j] += qv * Ms[d * 33 + c16 + j];
        }
        uint32_t pk[8];
        #pragma unroll
        for (int j = 0; j < 8; j++) {
            __half2 p = __floats2half2_rn(acc[2*j], acc[2*j+1]);
            pk[j] = *(uint32_t*)&p;
        }
        size_t off = ((size_t)b * 64 + r) * CH + h * HD + c16;
        uint4* dh = (uint4*)(g_t + off);
        dh[0] = make_uint4(pk[0], pk[1], pk[2], pk[3]);
        dh[1] = make_uint4(pk[4], pk[5], pk[6], pk[7]);
    }
}

// ---------------------------------------------------------------------------
extern "C" void kernel_launch(void* const* d_in, const int* in_sizes, int n_in,
                              void* d_out, int out_size) {
    (void)in_sizes; (void)n_in; (void)out_size;
    const float* x      = (const float*)d_in[0];
    const float* qkv_w  = (const float*)d_in[1];
    const float* qkv_b  = (const float*)d_in[2];
    const float* proj_w = (const float*)d_in[3];
    const float* proj_b = (const float*)d_in[4];
    const float* lk1    = (const float*)d_in[5];
    const float* lv1    = (const float*)d_in[6];
    const float* lk2    = (const float*)d_in[7];
    const float* lv2    = (const float*)d_in[8];

    static int inited = 0;
    static __half *xh, *wqh, *wql, *wph, *wpl, *th;
    static float *qkv;
    if (!inited) {
        cudaGetSymbolAddress((void**)&xh,  g_xh);
        cudaGetSymbolAddress((void**)&wqh, g_wqh);
        cudaGetSymbolAddress((void**)&wql, g_wql);
        cudaGetSymbolAddress((void**)&wph, g_wph);
        cudaGetSymbolAddress((void**)&wpl, g_wpl);
        cudaGetSymbolAddress((void**)&th,  g_t);
        cudaGetSymbolAddress((void**)&qkv, g_qkv);
        cudaFuncSetAttribute(gemm_f16,
                             cudaFuncAttributeMaxDynamicSharedMemorySize, GEMM_SMEM);
        inited = 1;
    }

    prep_kernel<<<2048, 256>>>(x, qkv_w, proj_w, lk1, lv1, lk2, lv2);
    gemm_f16<<<dim3(NQKV/128, MTOT/128), 256, GEMM_SMEM>>>(
        xh, wqh, wql, qkv_b, qkv, NQKV, 0);
    mid_kernel<<<dim3(BATCH, NH), 128>>>();
    gemm_f16<<<dim3(CH/128, MTOT/128), 256, GEMM_SMEM>>>(
        th, wph, wpl, proj_b, (float*)d_out, CH, 1);
}